// round 14
// baseline (speedup 1.0000x reference)
#include <cuda_runtime.h>
#include <cuda_fp16.h>
#include <cstdint>

// ---------------------------------------------------------------------------
// y[b,i,t,e] = sum_{j,d} x[b,j,t,d] * sign[i,j]*W[widx[i,j]][d,e]*beta[e]
// == per-b GEMM: Y[4096 x 1024] = X[4096 x 1024(k=j,d)] @ WfT^T,
//    WfT[n=(i,e)][k=(j,d)] row-major (B operand).
//
// fp16 m16n8k16 legacy mma.sync. This round: CTA tile M128xN256, 512 thr,
// 1 CTA/SM, SW128 unpadded smem, NS=4 -> each cp.async stage gets ~2 kc of
// flight time (was ~1), removing the cp_wait exposure that cost ~4 cyc/MMA.
// Split conv_x (DRAM-floor, 27us) + prep unchanged.
// ---------------------------------------------------------------------------

constexpr int NS = 4;                          // pipeline stages
constexpr int A_TILE = 128 * 128;              // 128 rows x 64 fp16 (SW128)
constexpr int B_TILE = 256 * 128;              // 256 rows x 64 fp16 (SW128)
constexpr int STAGE_BYTES = A_TILE + B_TILE;   // 49152
constexpr int SMEM_BYTES = NS * STAGE_BYTES;   // 196608 (<= 227KB), 1 CTA/SM
constexpr int B_OFF = A_TILE;

// x converted to fp16, same [b][j][t][d] layout (67 MB scratch).
__device__ __half g_xh[8u * 8u * 4096u * 128u];
// Fused weight, transposed, fp16: WfT[n=(i,e)][k=(j,d)], beta+sign folded in.
__device__ __half g_WfT[1024 * 1024];

__constant__ float c_sign[64] = {
 +1,-1,-1,-1,-1,-1,-1,-1,
 +1,+1,+1,-1,+1,-1,-1,+1,
 +1,-1,+1,+1,+1,+1,-1,-1,
 +1,+1,-1,+1,+1,-1,+1,-1,
 +1,-1,-1,-1,+1,+1,+1,+1,
 +1,+1,-1,+1,-1,+1,-1,+1,
 +1,+1,+1,-1,-1,+1,+1,-1,
 +1,-1,+1,+1,-1,-1,+1,+1};
__constant__ int c_widx[64] = {
 0,1,2,3,4,5,6,7,
 1,0,3,2,5,4,7,6,
 2,3,0,1,6,7,4,5,
 3,2,1,0,7,6,5,4,
 4,5,6,7,0,1,2,3,
 5,4,7,6,1,0,3,2,
 6,7,4,5,2,3,0,1,
 7,6,5,4,3,2,1,0};

// ---------------- PTX helpers ----------------
__device__ __forceinline__ void cp_async16(uint32_t dst, const void* src) {
    asm volatile("cp.async.cg.shared.global [%0], [%1], 16;\n"
                 :: "r"(dst), "l"(src) : "memory");
}
__device__ __forceinline__ void cp_commit() {
    asm volatile("cp.async.commit_group;\n" ::: "memory");
}
template <int N>
__device__ __forceinline__ void cp_wait() {
    asm volatile("cp.async.wait_group %0;\n" :: "n"(N) : "memory");
}
__device__ __forceinline__ uint32_t smem_u32(const void* p) {
    uint32_t a;
    asm("{ .reg .u64 t; cvta.to.shared.u64 t, %1; cvt.u32.u64 %0, t; }"
        : "=r"(a) : "l"(p));
    return a;
}
__device__ __forceinline__ void ldsm_x4(uint32_t* r, uint32_t addr) {
    asm volatile("ldmatrix.sync.aligned.m8n8.x4.shared.b16 {%0,%1,%2,%3}, [%4];"
                 : "=r"(r[0]), "=r"(r[1]), "=r"(r[2]), "=r"(r[3]) : "r"(addr));
}
// pack2(a,b): fp16(a) in low 16 bits, fp16(b) in high 16 bits (RN).
__device__ __forceinline__ uint32_t pack2(float a, float b) {
    uint32_t r;
    asm("cvt.rn.f16x2.f32 %0, %1, %2;" : "=r"(r) : "f"(b), "f"(a));
    return r;
}

// ---------------- x fp32 -> fp16 conversion (32B out per thread) ----------------
__global__ void conv_x_kernel(const float* __restrict__ x) {
    const size_t i = (size_t)blockIdx.x * 256 + threadIdx.x;   // 4.19M threads
    const float4* xv = reinterpret_cast<const float4*>(x);
    const float4 a = xv[2 * i];
    const float4 b = xv[2 * i + 1];
    uint4 o;
    o.x = pack2(a.x, a.y);
    o.y = pack2(a.z, a.w);
    o.z = pack2(b.x, b.y);
    o.w = pack2(b.z, b.w);
    reinterpret_cast<uint4*>(g_xh)[i] = o;
}

// ---------------- Wf prep (transposed, fp16) ----------------
__global__ void prep_wf_kernel(const float* __restrict__ W,
                               const float* __restrict__ beta) {
    __shared__ float s[32][33];
    const int kb = blockIdx.x * 32;   // k tile
    const int nb = blockIdx.y * 32;   // n tile
    const int i = nb >> 7, j = kb >> 7;
    const float sg = c_sign[i * 8 + j];
    const int w = c_widx[i * 8 + j];
    const int e0 = nb & 127, d0 = kb & 127;
    s[threadIdx.y][threadIdx.x] =
        W[(w << 14) + (d0 + threadIdx.y) * 128 + (e0 + threadIdx.x)];
    __syncthreads();
    const float v = s[threadIdx.x][threadIdx.y] * sg * beta[e0 + threadIdx.y];
    g_WfT[(size_t)(nb + threadIdx.y) * 1024 + kb + threadIdx.x] =
        __float2half_rn(v);
}

// ---------------- main GEMM (M128 x N256, 512 threads, NS=4) ----------------
__global__ __launch_bounds__(512, 1)
void octo_gemm_kernel(float* __restrict__ y) {
    extern __shared__ __align__(128) char smc[];
    const uint32_t sbase = smem_u32(smc);
    const int tid = threadIdx.x;
    const int lane = tid & 31;
    const int warp = tid >> 5;
    const int warp_m = warp & 1;   // 2 warps over M (64 rows each)
    const int warp_n = warp >> 1;  // 8 warps over N (32 cols each)

    const int nb = blockIdx.x;         // 0..3 -> heads 2nb, 2nb+1
    const int t0 = blockIdx.y * 128;   // t tile
    const int b  = blockIdx.z;

    const __half* xb = g_xh + (size_t)b * (8u * 4096u * 128u);
    const __half* gB = g_WfT + ((size_t)nb * 256) * 1024;

    auto issue_stage = [&](int kc) {   // kc 0..15, K-chunk = 64 fp16
        const int s = kc & (NS - 1);
        const uint32_t a_base = sbase + (uint32_t)(s * STAGE_BYTES);
        const uint32_t b_base = a_base + B_OFF;
        const int j = kc >> 1;
        const int d0 = (kc & 1) * 64;
        const __half* srcA = xb + ((size_t)j * 4096 + t0) * 128 + d0;
        const __half* srcB = gB + kc * 64;
        #pragma unroll
        for (int it = 0; it < 2; it++) {          // A: 1024 chunks / 512 thr
            const int id = tid + 512 * it;
            const int r = id >> 3, ch = id & 7;
            const uint32_t off = (uint32_t)(r * 128 + ((ch * 16) ^ ((r & 7) * 16)));
            cp_async16(a_base + off, srcA + (size_t)r * 128 + ch * 8);
        }
        #pragma unroll
        for (int it = 0; it < 4; it++) {          // B: 2048 chunks / 512 thr
            const int id = tid + 512 * it;
            const int r = id >> 3, ch = id & 7;
            const uint32_t off = (uint32_t)(r * 128 + ((ch * 16) ^ ((r & 7) * 16)));
            cp_async16(b_base + off, srcB + (size_t)r * 1024 + ch * 8);
        }
    };

    float acc[4][4][4];
    #pragma unroll
    for (int mt = 0; mt < 4; mt++)
        #pragma unroll
        for (int nt = 0; nt < 4; nt++)
            #pragma unroll
            for (int c = 0; c < 4; c++) acc[mt][nt][c] = 0.0f;

    // ldmatrix lane addressing (SW128, byte offsets within a stage)
    const int aRow = warp_m * 64 + ((lane >> 3) & 1) * 8 + (lane & 7);
    const uint32_t aAdj = (uint32_t)(((lane >> 4) & 1) << 4);
    const uint32_t aXor = (uint32_t)((aRow & 7) << 4);
    const int bRow = warp_n * 32 + ((lane >> 4) & 1) * 8 + (lane & 7);
    const uint32_t bAdj = (uint32_t)(((lane >> 3) & 1) << 4);
    const uint32_t bXor = (uint32_t)((bRow & 7) << 4);

    uint32_t aF[2][4][4];   // [buf][mt][reg]
    uint32_t bF[2][2][4];   // [buf][pr][reg]: {b0,b1} of nt=2pr then 2pr+1

    auto prefetch = [&](int buf, uint32_t stg, int ks) {
        const uint32_t aco = (uint32_t)((ks << 5) | aAdj) ^ aXor;
        const uint32_t abase = stg + (uint32_t)(aRow * 128) + aco;
        #pragma unroll
        for (int mt = 0; mt < 4; mt++) ldsm_x4(aF[buf][mt], abase + mt * 2048);
        const uint32_t bco = (uint32_t)((ks << 5) | bAdj) ^ bXor;
        const uint32_t bbase = stg + (uint32_t)B_OFF + (uint32_t)(bRow * 128) + bco;
        #pragma unroll
        for (int pr = 0; pr < 2; pr++) ldsm_x4(bF[buf][pr], bbase + pr * 2048);
    };
    auto do_mmas = [&](int buf) {
        #pragma unroll
        for (int mt = 0; mt < 4; mt++)
            #pragma unroll
            for (int nt = 0; nt < 4; nt++) {
                const uint32_t* bp = &bF[buf][nt >> 1][(nt & 1) * 2];
                asm volatile(
                    "mma.sync.aligned.m16n8k16.row.col.f32.f16.f16.f32 "
                    "{%0,%1,%2,%3}, {%4,%5,%6,%7}, {%8,%9}, {%0,%1,%2,%3};\n"
                    : "+f"(acc[mt][nt][0]), "+f"(acc[mt][nt][1]),
                      "+f"(acc[mt][nt][2]), "+f"(acc[mt][nt][3])
                    : "r"(aF[buf][mt][0]), "r"(aF[buf][mt][1]),
                      "r"(aF[buf][mt][2]), "r"(aF[buf][mt][3]),
                      "r"(bp[0]), "r"(bp[1]));
            }
    };

    // prologue: NS-1 = 3 stages in flight, stage 0 ready, ks0 frags loaded
    issue_stage(0); cp_commit();
    issue_stage(1); cp_commit();
    issue_stage(2); cp_commit();
    cp_wait<NS - 2>();
    __syncthreads();
    prefetch(0, sbase, 0);

    for (int kc = 0; kc < 16; kc++) {
        const uint32_t stg = sbase + (uint32_t)((kc & (NS - 1)) * STAGE_BYTES);

        if (kc + 3 < 16) issue_stage(kc + 3);
        cp_commit();                      // empty tail groups keep counts uniform

        #pragma unroll
        for (int ks = 0; ks < 3; ks++) {  // ks0..2: prefetch ks+1, then MMA ks
            prefetch((ks + 1) & 1, stg, ks + 1);
            do_mmas(ks & 1);
        }

        if (kc < 15) {
            // wait (2 stages in flight allowed) + next-stage ks0 ldmatrix,
            // hidden behind ks=3 MMAs below
            cp_wait<NS - 2>();
            __syncthreads();
            prefetch(0, sbase + (uint32_t)(((kc + 1) & (NS - 1)) * STAGE_BYTES), 0);
        }
        do_mmas(1);                       // ks=3 (fragments loaded at ks==2)
    }

    // epilogue: n_global = nb*256 + warp_n*32 + ...; head i = n>>7, e = n&127
    const int n_warp = nb * 256 + warp_n * 32;
    const int ih = n_warp >> 7;
    const int e_base = (n_warp & 127) + (lane & 3) * 2;
    float* yb = y + ((size_t)b * 8 + ih) * 4096u * 128u;
    #pragma unroll
    for (int mt = 0; mt < 4; mt++) {
        const int row = t0 + warp_m * 64 + mt * 16 + (lane >> 2);
        #pragma unroll
        for (int nt = 0; nt < 4; nt++) {
            const int e = e_base + nt * 8;
            *reinterpret_cast<float2*>(yb + (size_t)row * 128 + e) =
                make_float2(acc[mt][nt][0], acc[mt][nt][1]);
            *reinterpret_cast<float2*>(yb + (size_t)(row + 8) * 128 + e) =
                make_float2(acc[mt][nt][2], acc[mt][nt][3]);
        }
    }
}

extern "C" void kernel_launch(void* const* d_in, const int* in_sizes, int n_in,
                              void* d_out, int out_size) {
    const float* x    = (const float*)d_in[0];   // [8,8,4096,128] fp32
    const float* W    = (const float*)d_in[1];   // [8,128,128] fp32
    const float* beta = (const float*)d_in[2];   // [128] fp32
    float* y = (float*)d_out;                    // [8,8,4096,128] fp32
    (void)in_sizes; (void)n_in; (void)out_size;

    cudaFuncSetAttribute(octo_gemm_kernel,
                         cudaFuncAttributeMaxDynamicSharedMemorySize, SMEM_BYTES);

    conv_x_kernel<<<16384, 256>>>(x);                    // 33.5M elems / 8 per thread
    prep_wf_kernel<<<dim3(32, 32), dim3(32, 32)>>>(W, beta);

    dim3 grid(4, 32, 8);   // n-tiles fastest: 4 CTAs share each x tile in L2
    octo_gemm_kernel<<<grid, 512, SMEM_BYTES>>>(y);
}

// round 15
// speedup vs baseline: 1.0001x; 1.0001x over previous
#include <cuda_runtime.h>
#include <cuda_fp16.h>
#include <cstdint>

// ---------------------------------------------------------------------------
// y[b,i,t,e] = sum_{j,d} x[b,j,t,d] * sign[i,j]*W[widx[i,j]][d,e]*beta[e]
// == per-b GEMM: Y[4096 x 1024] = X[4096 x 1024(k=j,d)] @ WfT^T,
//    WfT[n=(i,e)][k=(j,d)] row-major (B operand).
//
// fp16 m16n8k16 legacy mma.sync. This round: CTA tile M128xN256, 512 thr,
// 1 CTA/SM, SW128 unpadded smem, NS=4 -> each cp.async stage gets ~2 kc of
// flight time (was ~1), removing the cp_wait exposure that cost ~4 cyc/MMA.
// Split conv_x (DRAM-floor, 27us) + prep unchanged.
// ---------------------------------------------------------------------------

constexpr int NS = 4;                          // pipeline stages
constexpr int A_TILE = 128 * 128;              // 128 rows x 64 fp16 (SW128)
constexpr int B_TILE = 256 * 128;              // 256 rows x 64 fp16 (SW128)
constexpr int STAGE_BYTES = A_TILE + B_TILE;   // 49152
constexpr int SMEM_BYTES = NS * STAGE_BYTES;   // 196608 (<= 227KB), 1 CTA/SM
constexpr int B_OFF = A_TILE;

// x converted to fp16, same [b][j][t][d] layout (67 MB scratch).
__device__ __half g_xh[8u * 8u * 4096u * 128u];
// Fused weight, transposed, fp16: WfT[n=(i,e)][k=(j,d)], beta+sign folded in.
__device__ __half g_WfT[1024 * 1024];

__constant__ float c_sign[64] = {
 +1,-1,-1,-1,-1,-1,-1,-1,
 +1,+1,+1,-1,+1,-1,-1,+1,
 +1,-1,+1,+1,+1,+1,-1,-1,
 +1,+1,-1,+1,+1,-1,+1,-1,
 +1,-1,-1,-1,+1,+1,+1,+1,
 +1,+1,-1,+1,-1,+1,-1,+1,
 +1,+1,+1,-1,-1,+1,+1,-1,
 +1,-1,+1,+1,-1,-1,+1,+1};
__constant__ int c_widx[64] = {
 0,1,2,3,4,5,6,7,
 1,0,3,2,5,4,7,6,
 2,3,0,1,6,7,4,5,
 3,2,1,0,7,6,5,4,
 4,5,6,7,0,1,2,3,
 5,4,7,6,1,0,3,2,
 6,7,4,5,2,3,0,1,
 7,6,5,4,3,2,1,0};

// ---------------- PTX helpers ----------------
__device__ __forceinline__ void cp_async16(uint32_t dst, const void* src) {
    asm volatile("cp.async.cg.shared.global [%0], [%1], 16;\n"
                 :: "r"(dst), "l"(src) : "memory");
}
__device__ __forceinline__ void cp_commit() {
    asm volatile("cp.async.commit_group;\n" ::: "memory");
}
template <int N>
__device__ __forceinline__ void cp_wait() {
    asm volatile("cp.async.wait_group %0;\n" :: "n"(N) : "memory");
}
__device__ __forceinline__ uint32_t smem_u32(const void* p) {
    uint32_t a;
    asm("{ .reg .u64 t; cvta.to.shared.u64 t, %1; cvt.u32.u64 %0, t; }"
        : "=r"(a) : "l"(p));
    return a;
}
__device__ __forceinline__ void ldsm_x4(uint32_t* r, uint32_t addr) {
    asm volatile("ldmatrix.sync.aligned.m8n8.x4.shared.b16 {%0,%1,%2,%3}, [%4];"
                 : "=r"(r[0]), "=r"(r[1]), "=r"(r[2]), "=r"(r[3]) : "r"(addr));
}
// pack2(a,b): fp16(a) in low 16 bits, fp16(b) in high 16 bits (RN).
__device__ __forceinline__ uint32_t pack2(float a, float b) {
    uint32_t r;
    asm("cvt.rn.f16x2.f32 %0, %1, %2;" : "=r"(r) : "f"(b), "f"(a));
    return r;
}

// ---------------- x fp32 -> fp16 conversion (32B out per thread) ----------------
__global__ void conv_x_kernel(const float* __restrict__ x) {
    const size_t i = (size_t)blockIdx.x * 256 + threadIdx.x;   // 4.19M threads
    const float4* xv = reinterpret_cast<const float4*>(x);
    const float4 a = xv[2 * i];
    const float4 b = xv[2 * i + 1];
    uint4 o;
    o.x = pack2(a.x, a.y);
    o.y = pack2(a.z, a.w);
    o.z = pack2(b.x, b.y);
    o.w = pack2(b.z, b.w);
    reinterpret_cast<uint4*>(g_xh)[i] = o;
}

// ---------------- Wf prep (transposed, fp16) ----------------
__global__ void prep_wf_kernel(const float* __restrict__ W,
                               const float* __restrict__ beta) {
    __shared__ float s[32][33];
    const int kb = blockIdx.x * 32;   // k tile
    const int nb = blockIdx.y * 32;   // n tile
    const int i = nb >> 7, j = kb >> 7;
    const float sg = c_sign[i * 8 + j];
    const int w = c_widx[i * 8 + j];
    const int e0 = nb & 127, d0 = kb & 127;
    s[threadIdx.y][threadIdx.x] =
        W[(w << 14) + (d0 + threadIdx.y) * 128 + (e0 + threadIdx.x)];
    __syncthreads();
    const float v = s[threadIdx.x][threadIdx.y] * sg * beta[e0 + threadIdx.y];
    g_WfT[(size_t)(nb + threadIdx.y) * 1024 + kb + threadIdx.x] =
        __float2half_rn(v);
}

// ---------------- main GEMM (M128 x N256, 512 threads, NS=4) ----------------
__global__ __launch_bounds__(512, 1)
void octo_gemm_kernel(float* __restrict__ y) {
    extern __shared__ __align__(128) char smc[];
    const uint32_t sbase = smem_u32(smc);
    const int tid = threadIdx.x;
    const int lane = tid & 31;
    const int warp = tid >> 5;
    const int warp_m = warp & 1;   // 2 warps over M (64 rows each)
    const int warp_n = warp >> 1;  // 8 warps over N (32 cols each)

    const int nb = blockIdx.x;         // 0..3 -> heads 2nb, 2nb+1
    const int t0 = blockIdx.y * 128;   // t tile
    const int b  = blockIdx.z;

    const __half* xb = g_xh + (size_t)b * (8u * 4096u * 128u);
    const __half* gB = g_WfT + ((size_t)nb * 256) * 1024;

    auto issue_stage = [&](int kc) {   // kc 0..15, K-chunk = 64 fp16
        const int s = kc & (NS - 1);
        const uint32_t a_base = sbase + (uint32_t)(s * STAGE_BYTES);
        const uint32_t b_base = a_base + B_OFF;
        const int j = kc >> 1;
        const int d0 = (kc & 1) * 64;
        const __half* srcA = xb + ((size_t)j * 4096 + t0) * 128 + d0;
        const __half* srcB = gB + kc * 64;
        #pragma unroll
        for (int it = 0; it < 2; it++) {          // A: 1024 chunks / 512 thr
            const int id = tid + 512 * it;
            const int r = id >> 3, ch = id & 7;
            const uint32_t off = (uint32_t)(r * 128 + ((ch * 16) ^ ((r & 7) * 16)));
            cp_async16(a_base + off, srcA + (size_t)r * 128 + ch * 8);
        }
        #pragma unroll
        for (int it = 0; it < 4; it++) {          // B: 2048 chunks / 512 thr
            const int id = tid + 512 * it;
            const int r = id >> 3, ch = id & 7;
            const uint32_t off = (uint32_t)(r * 128 + ((ch * 16) ^ ((r & 7) * 16)));
            cp_async16(b_base + off, srcB + (size_t)r * 1024 + ch * 8);
        }
    };

    float acc[4][4][4];
    #pragma unroll
    for (int mt = 0; mt < 4; mt++)
        #pragma unroll
        for (int nt = 0; nt < 4; nt++)
            #pragma unroll
            for (int c = 0; c < 4; c++) acc[mt][nt][c] = 0.0f;

    // ldmatrix lane addressing (SW128, byte offsets within a stage)
    const int aRow = warp_m * 64 + ((lane >> 3) & 1) * 8 + (lane & 7);
    const uint32_t aAdj = (uint32_t)(((lane >> 4) & 1) << 4);
    const uint32_t aXor = (uint32_t)((aRow & 7) << 4);
    const int bRow = warp_n * 32 + ((lane >> 4) & 1) * 8 + (lane & 7);
    const uint32_t bAdj = (uint32_t)(((lane >> 3) & 1) << 4);
    const uint32_t bXor = (uint32_t)((bRow & 7) << 4);

    uint32_t aF[2][4][4];   // [buf][mt][reg]
    uint32_t bF[2][2][4];   // [buf][pr][reg]: {b0,b1} of nt=2pr then 2pr+1

    auto prefetch = [&](int buf, uint32_t stg, int ks) {
        const uint32_t aco = (uint32_t)((ks << 5) | aAdj) ^ aXor;
        const uint32_t abase = stg + (uint32_t)(aRow * 128) + aco;
        #pragma unroll
        for (int mt = 0; mt < 4; mt++) ldsm_x4(aF[buf][mt], abase + mt * 2048);
        const uint32_t bco = (uint32_t)((ks << 5) | bAdj) ^ bXor;
        const uint32_t bbase = stg + (uint32_t)B_OFF + (uint32_t)(bRow * 128) + bco;
        #pragma unroll
        for (int pr = 0; pr < 2; pr++) ldsm_x4(bF[buf][pr], bbase + pr * 2048);
    };
    auto do_mmas = [&](int buf) {
        #pragma unroll
        for (int mt = 0; mt < 4; mt++)
            #pragma unroll
            for (int nt = 0; nt < 4; nt++) {
                const uint32_t* bp = &bF[buf][nt >> 1][(nt & 1) * 2];
                asm volatile(
                    "mma.sync.aligned.m16n8k16.row.col.f32.f16.f16.f32 "
                    "{%0,%1,%2,%3}, {%4,%5,%6,%7}, {%8,%9}, {%0,%1,%2,%3};\n"
                    : "+f"(acc[mt][nt][0]), "+f"(acc[mt][nt][1]),
                      "+f"(acc[mt][nt][2]), "+f"(acc[mt][nt][3])
                    : "r"(aF[buf][mt][0]), "r"(aF[buf][mt][1]),
                      "r"(aF[buf][mt][2]), "r"(aF[buf][mt][3]),
                      "r"(bp[0]), "r"(bp[1]));
            }
    };

    // prologue: NS-1 = 3 stages in flight, stage 0 ready, ks0 frags loaded
    issue_stage(0); cp_commit();
    issue_stage(1); cp_commit();
    issue_stage(2); cp_commit();
    cp_wait<NS - 2>();
    __syncthreads();
    prefetch(0, sbase, 0);

    for (int kc = 0; kc < 16; kc++) {
        const uint32_t stg = sbase + (uint32_t)((kc & (NS - 1)) * STAGE_BYTES);

        if (kc + 3 < 16) issue_stage(kc + 3);
        cp_commit();                      // empty tail groups keep counts uniform

        #pragma unroll
        for (int ks = 0; ks < 3; ks++) {  // ks0..2: prefetch ks+1, then MMA ks
            prefetch((ks + 1) & 1, stg, ks + 1);
            do_mmas(ks & 1);
        }

        if (kc < 15) {
            // wait (2 stages in flight allowed) + next-stage ks0 ldmatrix,
            // hidden behind ks=3 MMAs below
            cp_wait<NS - 2>();
            __syncthreads();
            prefetch(0, sbase + (uint32_t)(((kc + 1) & (NS - 1)) * STAGE_BYTES), 0);
        }
        do_mmas(1);                       // ks=3 (fragments loaded at ks==2)
    }

    // epilogue: n_global = nb*256 + warp_n*32 + ...; head i = n>>7, e = n&127
    const int n_warp = nb * 256 + warp_n * 32;
    const int ih = n_warp >> 7;
    const int e_base = (n_warp & 127) + (lane & 3) * 2;
    float* yb = y + ((size_t)b * 8 + ih) * 4096u * 128u;
    #pragma unroll
    for (int mt = 0; mt < 4; mt++) {
        const int row = t0 + warp_m * 64 + mt * 16 + (lane >> 2);
        #pragma unroll
        for (int nt = 0; nt < 4; nt++) {
            const int e = e_base + nt * 8;
            *reinterpret_cast<float2*>(yb + (size_t)row * 128 + e) =
                make_float2(acc[mt][nt][0], acc[mt][nt][1]);
            *reinterpret_cast<float2*>(yb + (size_t)(row + 8) * 128 + e) =
                make_float2(acc[mt][nt][2], acc[mt][nt][3]);
        }
    }
}

extern "C" void kernel_launch(void* const* d_in, const int* in_sizes, int n_in,
                              void* d_out, int out_size) {
    const float* x    = (const float*)d_in[0];   // [8,8,4096,128] fp32
    const float* W    = (const float*)d_in[1];   // [8,128,128] fp32
    const float* beta = (const float*)d_in[2];   // [128] fp32
    float* y = (float*)d_out;                    // [8,8,4096,128] fp32
    (void)in_sizes; (void)n_in; (void)out_size;

    cudaFuncSetAttribute(octo_gemm_kernel,
                         cudaFuncAttributeMaxDynamicSharedMemorySize, SMEM_BYTES);

    conv_x_kernel<<<16384, 256>>>(x);                    // 33.5M elems / 8 per thread
    prep_wf_kernel<<<dim3(32, 32), dim3(32, 32)>>>(W, beta);

    dim3 grid(4, 32, 8);   // n-tiles fastest: 4 CTAs share each x tile in L2
    octo_gemm_kernel<<<grid, 512, SMEM_BYTES>>>(y);
}

// round 16
// speedup vs baseline: 1.0760x; 1.0759x over previous
#include <cuda_runtime.h>
#include <cuda_fp16.h>
#include <cstdint>

// ---------------------------------------------------------------------------
// y[b,i,t,e] = sum_{j,d} x[b,j,t,d] * sign[i,j]*W[widx[i,j]][d,e]*beta[e]
// == per-b GEMM: Y[4096 x 1024] = X[4096 x 1024(k=j,d)] @ WfT^T,
//    WfT[n=(i,e)][k=(j,d)] row-major (B operand).
//
// fp16 m16n8k16 legacy mma.sync. This round: 64x64 WARP tiles (8 warps,
// CTA M128xN256) -> 32-MMA bursts per 8 ldmatrix.x4, halving the
// fragment-load duty cycle that was bubbling the tensor pipe.
// Split conv_x (DRAM-floor, 27us) + prep unchanged.
// ---------------------------------------------------------------------------

constexpr int NS = 3;                          // pipeline stages
constexpr int A_TILE = 128 * 128;              // 128 rows x 64 fp16 (SW128)
constexpr int B_TILE = 256 * 128;              // 256 rows x 64 fp16 (SW128)
constexpr int STAGE_BYTES = A_TILE + B_TILE;   // 49152
constexpr int SMEM_BYTES = NS * STAGE_BYTES;   // 147456 -> 1 CTA/SM
constexpr int B_OFF = A_TILE;

// x converted to fp16, same [b][j][t][d] layout (67 MB scratch).
__device__ __half g_xh[8u * 8u * 4096u * 128u];
// Fused weight, transposed, fp16: WfT[n=(i,e)][k=(j,d)], beta+sign folded in.
__device__ __half g_WfT[1024 * 1024];

__constant__ float c_sign[64] = {
 +1,-1,-1,-1,-1,-1,-1,-1,
 +1,+1,+1,-1,+1,-1,-1,+1,
 +1,-1,+1,+1,+1,+1,-1,-1,
 +1,+1,-1,+1,+1,-1,+1,-1,
 +1,-1,-1,-1,+1,+1,+1,+1,
 +1,+1,-1,+1,-1,+1,-1,+1,
 +1,+1,+1,-1,-1,+1,+1,-1,
 +1,-1,+1,+1,-1,-1,+1,+1};
__constant__ int c_widx[64] = {
 0,1,2,3,4,5,6,7,
 1,0,3,2,5,4,7,6,
 2,3,0,1,6,7,4,5,
 3,2,1,0,7,6,5,4,
 4,5,6,7,0,1,2,3,
 5,4,7,6,1,0,3,2,
 6,7,4,5,2,3,0,1,
 7,6,5,4,3,2,1,0};

// ---------------- PTX helpers ----------------
__device__ __forceinline__ void cp_async16(uint32_t dst, const void* src) {
    asm volatile("cp.async.cg.shared.global [%0], [%1], 16;\n"
                 :: "r"(dst), "l"(src) : "memory");
}
__device__ __forceinline__ void cp_commit() {
    asm volatile("cp.async.commit_group;\n" ::: "memory");
}
template <int N>
__device__ __forceinline__ void cp_wait() {
    asm volatile("cp.async.wait_group %0;\n" :: "n"(N) : "memory");
}
__device__ __forceinline__ uint32_t smem_u32(const void* p) {
    uint32_t a;
    asm("{ .reg .u64 t; cvta.to.shared.u64 t, %1; cvt.u32.u64 %0, t; }"
        : "=r"(a) : "l"(p));
    return a;
}
__device__ __forceinline__ void ldsm_x4(uint32_t* r, uint32_t addr) {
    asm volatile("ldmatrix.sync.aligned.m8n8.x4.shared.b16 {%0,%1,%2,%3}, [%4];"
                 : "=r"(r[0]), "=r"(r[1]), "=r"(r[2]), "=r"(r[3]) : "r"(addr));
}
// pack2(a,b): fp16(a) in low 16 bits, fp16(b) in high 16 bits (RN).
__device__ __forceinline__ uint32_t pack2(float a, float b) {
    uint32_t r;
    asm("cvt.rn.f16x2.f32 %0, %1, %2;" : "=r"(r) : "f"(b), "f"(a));
    return r;
}

// ---------------- x fp32 -> fp16 conversion (32B out per thread) ----------------
__global__ void conv_x_kernel(const float* __restrict__ x) {
    const size_t i = (size_t)blockIdx.x * 256 + threadIdx.x;   // 4.19M threads
    const float4* xv = reinterpret_cast<const float4*>(x);
    const float4 a = xv[2 * i];
    const float4 b = xv[2 * i + 1];
    uint4 o;
    o.x = pack2(a.x, a.y);
    o.y = pack2(a.z, a.w);
    o.z = pack2(b.x, b.y);
    o.w = pack2(b.z, b.w);
    reinterpret_cast<uint4*>(g_xh)[i] = o;
}

// ---------------- Wf prep (transposed, fp16) ----------------
__global__ void prep_wf_kernel(const float* __restrict__ W,
                               const float* __restrict__ beta) {
    __shared__ float s[32][33];
    const int kb = blockIdx.x * 32;   // k tile
    const int nb = blockIdx.y * 32;   // n tile
    const int i = nb >> 7, j = kb >> 7;
    const float sg = c_sign[i * 8 + j];
    const int w = c_widx[i * 8 + j];
    const int e0 = nb & 127, d0 = kb & 127;
    s[threadIdx.y][threadIdx.x] =
        W[(w << 14) + (d0 + threadIdx.y) * 128 + (e0 + threadIdx.x)];
    __syncthreads();
    const float v = s[threadIdx.x][threadIdx.y] * sg * beta[e0 + threadIdx.y];
    g_WfT[(size_t)(nb + threadIdx.y) * 1024 + kb + threadIdx.x] =
        __float2half_rn(v);
}

// ---------------- main GEMM (M128 x N256, 256 thr, 64x64 warp tiles) ----------------
__global__ __launch_bounds__(256, 1)
void octo_gemm_kernel(float* __restrict__ y) {
    extern __shared__ __align__(128) char smc[];
    const uint32_t sbase = smem_u32(smc);
    const int tid = threadIdx.x;
    const int lane = tid & 31;
    const int warp = tid >> 5;
    const int warp_m = warp & 1;   // 2 warps over M (64 rows each)
    const int warp_n = warp >> 1;  // 4 warps over N (64 cols each)

    const int nb = blockIdx.x;         // 0..3 -> heads 2nb, 2nb+1
    const int t0 = blockIdx.y * 128;   // t tile
    const int b  = blockIdx.z;

    const __half* xb = g_xh + (size_t)b * (8u * 4096u * 128u);
    const __half* gB = g_WfT + ((size_t)nb * 256) * 1024;

    auto issue_stage = [&](int kc) {   // kc 0..15, K-chunk = 64 fp16
        const int s = kc % NS;
        const uint32_t a_base = sbase + (uint32_t)(s * STAGE_BYTES);
        const uint32_t b_base = a_base + B_OFF;
        const int j = kc >> 1;
        const int d0 = (kc & 1) * 64;
        const __half* srcA = xb + ((size_t)j * 4096 + t0) * 128 + d0;
        const __half* srcB = gB + kc * 64;
        #pragma unroll
        for (int it = 0; it < 4; it++) {          // A: 1024 chunks / 256 thr
            const int id = tid + 256 * it;
            const int r = id >> 3, ch = id & 7;
            const uint32_t off = (uint32_t)(r * 128 + ((ch * 16) ^ ((r & 7) * 16)));
            cp_async16(a_base + off, srcA + (size_t)r * 128 + ch * 8);
        }
        #pragma unroll
        for (int it = 0; it < 8; it++) {          // B: 2048 chunks / 256 thr
            const int id = tid + 256 * it;
            const int r = id >> 3, ch = id & 7;
            const uint32_t off = (uint32_t)(r * 128 + ((ch * 16) ^ ((r & 7) * 16)));
            cp_async16(b_base + off, srcB + (size_t)r * 1024 + ch * 8);
        }
    };

    float acc[4][8][4];
    #pragma unroll
    for (int mt = 0; mt < 4; mt++)
        #pragma unroll
        for (int nt = 0; nt < 8; nt++)
            #pragma unroll
            for (int c = 0; c < 4; c++) acc[mt][nt][c] = 0.0f;

    // ldmatrix lane addressing (SW128, byte offsets within a stage)
    const int aRow = warp_m * 64 + ((lane >> 3) & 1) * 8 + (lane & 7);
    const uint32_t aAdj = (uint32_t)(((lane >> 4) & 1) << 4);
    const uint32_t aXor = (uint32_t)((aRow & 7) << 4);
    const int bRow = warp_n * 64 + ((lane >> 4) & 1) * 8 + (lane & 7);
    const uint32_t bAdj = (uint32_t)(((lane >> 3) & 1) << 4);
    const uint32_t bXor = (uint32_t)((bRow & 7) << 4);

    uint32_t aF[2][4][4];   // [buf][mt][reg]
    uint32_t bF[2][4][4];   // [buf][pr][reg]: {b0,b1} of nt=2pr then 2pr+1

    auto prefetch = [&](int buf, uint32_t stg, int ks) {
        const uint32_t aco = (uint32_t)((ks << 5) | aAdj) ^ aXor;
        const uint32_t abase = stg + (uint32_t)(aRow * 128) + aco;
        #pragma unroll
        for (int mt = 0; mt < 4; mt++) ldsm_x4(aF[buf][mt], abase + mt * 2048);
        const uint32_t bco = (uint32_t)((ks << 5) | bAdj) ^ bXor;
        const uint32_t bbase = stg + (uint32_t)B_OFF + (uint32_t)(bRow * 128) + bco;
        #pragma unroll
        for (int pr = 0; pr < 4; pr++) ldsm_x4(bF[buf][pr], bbase + pr * 2048);
    };
    auto do_mmas = [&](int buf) {
        #pragma unroll
        for (int mt = 0; mt < 4; mt++)
            #pragma unroll
            for (int nt = 0; nt < 8; nt++) {
                const uint32_t* bp = &bF[buf][nt >> 1][(nt & 1) * 2];
                asm volatile(
                    "mma.sync.aligned.m16n8k16.row.col.f32.f16.f16.f32 "
                    "{%0,%1,%2,%3}, {%4,%5,%6,%7}, {%8,%9}, {%0,%1,%2,%3};\n"
                    : "+f"(acc[mt][nt][0]), "+f"(acc[mt][nt][1]),
                      "+f"(acc[mt][nt][2]), "+f"(acc[mt][nt][3])
                    : "r"(aF[buf][mt][0]), "r"(aF[buf][mt][1]),
                      "r"(aF[buf][mt][2]), "r"(aF[buf][mt][3]),
                      "r"(bp[0]), "r"(bp[1]));
            }
    };

    // prologue: NS-1 = 2 stages in flight, stage 0 ready, ks0 frags loaded
    issue_stage(0); cp_commit();
    issue_stage(1); cp_commit();
    cp_wait<NS - 2>();
    __syncthreads();
    prefetch(0, sbase, 0);

    for (int kc = 0; kc < 16; kc++) {
        const uint32_t stg = sbase + (uint32_t)((kc % NS) * STAGE_BYTES);

        if (kc + 2 < 16) issue_stage(kc + 2);
        cp_commit();                      // empty tail groups keep counts uniform

        #pragma unroll
        for (int ks = 0; ks < 3; ks++) {  // ks0..2: prefetch ks+1, then MMA ks
            prefetch((ks + 1) & 1, stg, ks + 1);
            do_mmas(ks & 1);
        }

        if (kc < 15) {
            // wait + next-stage ks0 ldmatrix hidden behind ks=3 MMAs below
            cp_wait<NS - 2>();
            __syncthreads();
            prefetch(0, sbase + (uint32_t)(((kc + 1) % NS) * STAGE_BYTES), 0);
        }
        do_mmas(1);                       // ks=3 (fragments loaded at ks==2)
    }

    // epilogue: n_warp = nb*256 + warp_n*64; head i = n>>7, e = n&127
    const int n_warp = nb * 256 + warp_n * 64;
    const int ih = n_warp >> 7;
    const int e_base = (n_warp & 127) + (lane & 3) * 2;
    float* yb = y + ((size_t)b * 8 + ih) * 4096u * 128u;
    #pragma unroll
    for (int mt = 0; mt < 4; mt++) {
        const int row = t0 + warp_m * 64 + mt * 16 + (lane >> 2);
        #pragma unroll
        for (int nt = 0; nt < 8; nt++) {
            const int e = e_base + nt * 8;
            *reinterpret_cast<float2*>(yb + (size_t)row * 128 + e) =
                make_float2(acc[mt][nt][0], acc[mt][nt][1]);
            *reinterpret_cast<float2*>(yb + (size_t)(row + 8) * 128 + e) =
                make_float2(acc[mt][nt][2], acc[mt][nt][3]);
        }
    }
}

extern "C" void kernel_launch(void* const* d_in, const int* in_sizes, int n_in,
                              void* d_out, int out_size) {
    const float* x    = (const float*)d_in[0];   // [8,8,4096,128] fp32
    const float* W    = (const float*)d_in[1];   // [8,128,128] fp32
    const float* beta = (const float*)d_in[2];   // [128] fp32
    float* y = (float*)d_out;                    // [8,8,4096,128] fp32
    (void)in_sizes; (void)n_in; (void)out_size;

    cudaFuncSetAttribute(octo_gemm_kernel,
                         cudaFuncAttributeMaxDynamicSharedMemorySize, SMEM_BYTES);

    conv_x_kernel<<<16384, 256>>>(x);                    // 33.5M elems / 8 per thread
    prep_wf_kernel<<<dim3(32, 32), dim3(32, 32)>>>(W, beta);

    dim3 grid(4, 32, 8);   // n-tiles fastest: 4 CTAs share each x tile in L2
    octo_gemm_kernel<<<grid, 256, SMEM_BYTES>>>(y);
}